// round 2
// baseline (speedup 1.0000x reference)
#include <cuda_runtime.h>
#include <math.h>

#define NM     1024
#define NA     32
#define ZD     64
#define HID    256
#define NT     10
#define NBOND  5
#define NEDGE  496
#define TOTA   32768
#define ATOM_OUT (TOTA*NT)

typedef unsigned long long ull;

__device__ __forceinline__ ull pk(float lo, float hi) {
    ull r; asm("mov.b64 %0,{%1,%2};" : "=l"(r) : "f"(lo), "f"(hi)); return r;
}
__device__ __forceinline__ float2 up(ull v) {
    float2 r; asm("mov.b64 {%0,%1},%2;" : "=f"(r.x), "=f"(r.y) : "l"(v)); return r;
}
__device__ __forceinline__ void fma2(ull& d, ull a, ull b) {
    asm("fma.rn.f32x2 %0,%1,%2,%0;" : "+l"(d) : "l"(a), "l"(b));
}

// ---------------- device scratch ----------------
__device__ float g_Gpart[256*4096];
__device__ float g_spart[256*64];
__device__ float g_G[4096];
__device__ float g_s[64];
__device__ __align__(16) float g_A[HID];
__device__ __align__(16) float g_B[HID];
__device__ float g_Wf[NBOND*ZD*ZD];

// ---------------- K1: fused bond-symmetrize + partial Gram/colsum ----------------
__global__ void k_prep_stats(const float* __restrict__ z, const float* __restrict__ bm) {
    __shared__ float zs[128*68];
    int tid = threadIdx.x;
    if (blockIdx.x >= 256) {       // prep: 80 blocks symmetrize bond matrix
        int idx = (blockIdx.x - 256)*256 + tid;
        if (idx < NBOND*ZD*ZD) {
            int t = idx >> 12, d = (idx >> 6) & 63, c = idx & 63;
            g_Wf[idx] = 0.5f*(bm[(t<<12)+(d<<6)+c] + bm[(t<<12)+(c<<6)+d]);
        }
        return;
    }
    int b = blockIdx.x;
    const float* zp = z + b*(128*64);
    for (int idx = tid; idx < 128*64; idx += 256)
        zs[(idx>>6)*68 + (idx&63)] = zp[idx];
    __syncthreads();

    int i0 = (tid & 15) << 2;
    int j0 = (tid >> 4) << 2;
    float acc[16];
#pragma unroll
    for (int k = 0; k < 16; k++) acc[k] = 0.f;
#pragma unroll 2
    for (int r = 0; r < 128; r++) {
        float zi[4], zj[4];
#pragma unroll
        for (int x = 0; x < 4; x++) { zi[x] = zs[r*68 + i0 + x]; zj[x] = zs[r*68 + j0 + x]; }
#pragma unroll
        for (int x = 0; x < 4; x++)
#pragma unroll
            for (int y = 0; y < 4; y++)
                acc[x*4+y] += zi[x]*zj[y];
    }
    float* gp = g_Gpart + b*4096;
#pragma unroll
    for (int k = 0; k < 16; k++) gp[tid*16 + k] = acc[k];

    if (tid < 64) {
        float s = 0.f;
        for (int r = 0; r < 128; r++) s += zs[r*68 + tid];
        g_spart[b*64 + tid] = s;
    }
}

// ---------------- K2: deterministic reduction ----------------
__global__ void k_reduce() {
    int e = blockIdx.x*256 + threadIdx.x;
    if (e < 4096) {
        float s = 0.f;
#pragma unroll 4
        for (int p = 0; p < 256; p++) s += g_Gpart[p*4096 + e];
        int tid = e >> 4, k = e & 15;
        int i = ((tid & 15) << 2) + (k >> 2);
        int j = ((tid >> 4) << 2) + (k & 3);
        g_G[i*64 + j] = s;
    } else if (e < 4160) {
        int c = e - 4096;
        float s = 0.f;
#pragma unroll 4
        for (int p = 0; p < 256; p++) s += g_spart[p*64 + c];
        g_s[c] = s;
    }
}

// ---------------- K3: analytic BN -> folded affine (4 j per block) ----------------
__global__ void k_finalize(const float* __restrict__ W1, const float* __restrict__ b1,
                           const float* __restrict__ gamma, const float* __restrict__ beta) {
    __shared__ float Gs[4096], ssh[64], Wc[4][64];
    __shared__ float red1[256], red2[256];
    int tid = threadIdx.x;
    for (int i = tid; i < 4096; i += 256) Gs[i] = g_G[i];
    if (tid < 64) ssh[tid] = g_s[tid];
    {   // stage 4 columns of W1: Wc[jj][c] = W1[c][j0+jj]
        int jj = tid >> 6, c = tid & 63;
        Wc[jj][c] = W1[c*HID + blockIdx.x*4 + jj];
    }
    __syncthreads();

    int d = tid & 63, jq = tid >> 6;
    float wdj = Wc[jq][d];
    float q = 0.f;
#pragma unroll
    for (int c = 0; c < 64; c++) q += Gs[d*64 + c] * Wc[jq][c];

    red1[tid] = ssh[d]*wdj;
    red2[tid] = q*wdj;
    __syncthreads();
    for (int off = 32; off > 0; off >>= 1) {
        if (d < off) { red1[tid] += red1[tid+off]; red2[tid] += red2[tid+off]; }
        __syncthreads();
    }
    if (d == 0) {
        int j = blockIdx.x*4 + jq;
        const float invN = 1.f/(float)TOTA;
        float sw = red1[tid], wGw = red2[tid];
        float bj = b1[j];
        float m1 = sw*invN + bj;
        float m2 = (wGw + 2.f*bj*sw)*invN + bj*bj;
        float var = m2 - m1*m1;
        float A = rsqrtf(var + 1e-5f) * gamma[j];
        g_A[j] = A;
        g_B[j] = (bj - m1)*A + beta[j];
    }
}

// ---------------- K4: fused GEMM1+BN+GELU+GEMM2, 64 rows/block, f32x2 ----------------
// smem: W1sh[64][256]=16384 | zsh[64][68]=4352 | W2t[10][260]=2600  (93344 B)
__global__ __launch_bounds__(256, 2)
void k_atoms(const float* __restrict__ z, const float* __restrict__ W1,
             const float* __restrict__ W2, const float* __restrict__ b2,
             float* __restrict__ out) {
    extern __shared__ float sm[];
    float* W1sh = sm;
    float* zsh  = sm + 16384;
    float* W2t  = sm + 16384 + 4352;
    int tid = threadIdx.x, b = blockIdx.x;
    const float* zp = z + b*(64*64);

    for (int i = tid; i < 16384; i += 256) W1sh[i] = W1[i];
    for (int i = tid; i < 4096;  i += 256) zsh[(i>>6)*68 + (i&63)] = zp[i];
    for (int i = tid; i < 2560;  i += 256) { int jj = i/10, kk = i%10; W2t[kk*260 + jj] = W2[i]; }
    __syncthreads();

    int lane = tid & 31, w = tid >> 5;
    int r0 = w << 3, j0 = lane << 3;     // 8 rows x 8 cols per thread
    ull acc[8][4];
#pragma unroll
    for (int x = 0; x < 8; x++)
#pragma unroll
        for (int y = 0; y < 4; y++) acc[x][y] = 0ull;

#pragma unroll 2
    for (int c = 0; c < 64; c++) {
        const float4* wp4 = (const float4*)&W1sh[(c<<8) + j0];
        float4 wa = wp4[0], wb = wp4[1];
        ull wv[4] = { pk(wa.x,wa.y), pk(wa.z,wa.w), pk(wb.x,wb.y), pk(wb.z,wb.w) };
#pragma unroll
        for (int x = 0; x < 8; x++) {
            float zr = zsh[(r0+x)*68 + c];
            ull zz = pk(zr, zr);
#pragma unroll
            for (int y = 0; y < 4; y++) fma2(acc[x][y], zz, wv[y]);
        }
    }

    // folded BN + exact GELU (cols j0..j0+7)
    float Av[8], Bv[8];
    { float4 a0 = *(const float4*)&g_A[j0], a1 = *(const float4*)&g_A[j0+4];
      float4 c0 = *(const float4*)&g_B[j0], c1 = *(const float4*)&g_B[j0+4];
      Av[0]=a0.x;Av[1]=a0.y;Av[2]=a0.z;Av[3]=a0.w;Av[4]=a1.x;Av[5]=a1.y;Av[6]=a1.z;Av[7]=a1.w;
      Bv[0]=c0.x;Bv[1]=c0.y;Bv[2]=c0.z;Bv[3]=c0.w;Bv[4]=c1.x;Bv[5]=c1.y;Bv[6]=c1.z;Bv[7]=c1.w; }
    float g[8][8];
#pragma unroll
    for (int x = 0; x < 8; x++)
#pragma unroll
        for (int y = 0; y < 4; y++) {
            float2 v = up(acc[x][y]);
            float t0 = v.x*Av[2*y]   + Bv[2*y];
            float t1 = v.y*Av[2*y+1] + Bv[2*y+1];
            g[x][2*y]   = 0.5f*t0*(1.f + erff(t0*0.70710678118654752f));
            g[x][2*y+1] = 0.5f*t1*(1.f + erff(t1*0.70710678118654752f));
        }

    __syncthreads();                          // done reading W1sh/zsh
    float* gsh = sm;                          // reuse as g[64][260]
#pragma unroll
    for (int x = 0; x < 8; x++)
#pragma unroll
        for (int y = 0; y < 4; y++)
            *(float2*)&gsh[(r0+x)*260 + j0 + 2*y] = make_float2(g[x][2*y], g[x][2*y+1]);
    __syncthreads();

    // GEMM2: 64x10 outputs via float4 dots
    for (int p = tid; p < 640; p += 256) {
        int r = p/10, k = p%10;
        const float4* gp4 = (const float4*)(gsh + r*260);
        const float4* wp4 = (const float4*)(W2t + k*260);
        float s = 0.f;
#pragma unroll
        for (int q = 0; q < 64; q++) {
            float4 a = gp4[q], ww = wp4[q];
            s += a.x*ww.x + a.y*ww.y + a.z*ww.z + a.w*ww.w;
        }
        out[(b*64 + r)*10 + k] = s + b2[k];
    }
}

// ---------------- K5: edges, 2 molecules/block, 512 threads, f32x2 ----------------
// smem: Wfsh[320][65]=20800 | zT 2x[64][34]=4352 | Ysh 2x[320][34]=21760  (187648 B)
__global__ __launch_bounds__(512, 1)
void k_edges(const float* __restrict__ z, float* __restrict__ out) {
    extern __shared__ float sm[];
    float* Wfsh = sm;
    float* zTb  = sm + 20800;
    float* Yb   = sm + 20800 + 4352;
    int tid = threadIdx.x;
    int half = tid >> 8, t = tid & 255;
    int mol = blockIdx.x*2 + half;
    const float* zp = z + mol*2048;
    float* zT = zTb + half*2176;    // [c][a] stride 34
    float* Yh = Yb  + half*10880;   // [td][a] stride 34

    for (int i = tid; i < 20480; i += 512)
        Wfsh[(i>>6)*65 + (i&63)] = g_Wf[i];
    for (int i = t; i < 2048; i += 256) {
        int a = i >> 6, c = i & 63;
        zT[c*34 + a] = zp[i];
    }
    __syncthreads();

    // ---- Y phase: Y[td][a] = sum_c Wf[td][c]*z[a][c], packed over atom pairs ----
    for (int tile = t; tile < 320; tile += 256) {
        int q = tile % 80, a0 = (tile/80) << 3;
        ull acc[4][4];
#pragma unroll
        for (int y = 0; y < 4; y++)
#pragma unroll
            for (int k = 0; k < 4; k++) acc[y][k] = 0ull;

#pragma unroll 2
        for (int c = 0; c < 64; c++) {
            ull wv[4];
#pragma unroll
            for (int y = 0; y < 4; y++) { float wq = Wfsh[(q + y*80)*65 + c]; wv[y] = pk(wq, wq); }
            ull zv[4];
#pragma unroll
            for (int k = 0; k < 4; k++) zv[k] = *(const ull*)&zT[c*34 + a0 + 2*k];
#pragma unroll
            for (int y = 0; y < 4; y++)
#pragma unroll
                for (int k = 0; k < 4; k++) fma2(acc[y][k], wv[y], zv[k]);
        }
#pragma unroll
        for (int y = 0; y < 4; y++)
#pragma unroll
            for (int k = 0; k < 4; k++)
                *(ull*)&Yh[(q + y*80)*34 + a0 + 2*k] = acc[y][k];
    }
    __syncthreads();

    // ---- edge phase: thread = 2i x 2j tile, packed over j pair, all 5 types ----
    int i0 = (t >> 4) << 1, j0 = (t & 15) << 1;
    ull L[2][5];
#pragma unroll
    for (int x = 0; x < 2; x++)
#pragma unroll
        for (int tt = 0; tt < 5; tt++) L[x][tt] = 0ull;

#pragma unroll 2
    for (int d = 0; d < 64; d++) {
        ull yv[5];
#pragma unroll
        for (int tt = 0; tt < 5; tt++) yv[tt] = *(const ull*)&Yh[(tt*64 + d)*34 + j0];
        float zi0 = zT[d*34 + i0], zi1 = zT[d*34 + i0 + 1];
        ull z0 = pk(zi0, zi0), z1 = pk(zi1, zi1);
#pragma unroll
        for (int tt = 0; tt < 5; tt++) { fma2(L[0][tt], z0, yv[tt]); fma2(L[1][tt], z1, yv[tt]); }
    }

    float* eout = out + ATOM_OUT + mol*(NEDGE*5);
#pragma unroll
    for (int x = 0; x < 2; x++) {
        float2 l0 = up(L[x][0]), l1 = up(L[x][1]), l2 = up(L[x][2]), l3 = up(L[x][3]), l4 = up(L[x][4]);
        int i = i0 + x;
#pragma unroll
        for (int y = 0; y < 2; y++) {
            int j = j0 + y;
            if (i < j) {
                float v0 = y ? l0.y : l0.x, v1 = y ? l1.y : l1.x, v2 = y ? l2.y : l2.x;
                float v3 = y ? l3.y : l3.x, v4 = y ? l4.y : l4.x;
                float m = fmaxf(fmaxf(fmaxf(v0, v1), fmaxf(v2, v3)), v4);
                float e0 = __expf(v0-m), e1 = __expf(v1-m), e2 = __expf(v2-m),
                      e3 = __expf(v3-m), e4 = __expf(v4-m);
                float inv = 1.f/(e0+e1+e2+e3+e4);
                int e = 31*i - (i*(i-1))/2 + (j - i - 1);
                float* dst = eout + e*5;
                dst[0] = e0*inv; dst[1] = e1*inv; dst[2] = e2*inv; dst[3] = e3*inv; dst[4] = e4*inv;
            }
        }
    }
}

// ---------------- launch ----------------
extern "C" void kernel_launch(void* const* d_in, const int* in_sizes, int n_in,
                              void* d_out, int out_size) {
    const float* z  = (const float*)d_in[0];
    const float* W1 = (const float*)d_in[1];
    const float* b1 = (const float*)d_in[2];
    const float* gm = (const float*)d_in[3];
    const float* bt = (const float*)d_in[4];
    const float* W2 = (const float*)d_in[5];
    const float* b2 = (const float*)d_in[6];
    const float* bm = (const float*)d_in[7];
    float* out = (float*)d_out;
    (void)in_sizes; (void)n_in; (void)out_size;

    const int SMEM_ATOMS = (16384 + 4352 + 2600) * 4;     // 93344 B
    const int SMEM_EDGES = (20800 + 4352 + 21760) * 4;    // 187648 B
    cudaFuncSetAttribute(k_atoms, cudaFuncAttributeMaxDynamicSharedMemorySize, SMEM_ATOMS);
    cudaFuncSetAttribute(k_edges, cudaFuncAttributeMaxDynamicSharedMemorySize, SMEM_EDGES);

    k_prep_stats<<<336, 256>>>(z, bm);
    k_reduce    <<<17,  256>>>();
    k_finalize  <<<64,  256>>>(W1, b1, gm, bt);
    k_atoms     <<<512, 256, SMEM_ATOMS>>>(z, W1, W2, b2, out);
    k_edges     <<<512, 512, SMEM_EDGES>>>(z, out);
}

// round 3
// speedup vs baseline: 1.0362x; 1.0362x over previous
#include <cuda_runtime.h>
#include <math.h>

#define NM     1024
#define NA     32
#define ZD     64
#define HID    256
#define NT     10
#define NBOND  5
#define NEDGE  496
#define TOTA   32768
#define ATOM_OUT (TOTA*NT)

typedef unsigned long long ull;

__device__ __forceinline__ float2 up(ull v) {
    float2 r; asm("mov.b64 {%0,%1},%2;" : "=f"(r.x), "=f"(r.y) : "l"(v)); return r;
}
__device__ __forceinline__ void fma2(ull& d, ull a, ull b) {
    asm("fma.rn.f32x2 %0,%1,%2,%0;" : "+l"(d) : "l"(a), "l"(b));
}

// ---------------- device scratch ----------------
__device__ float g_Gpart[256*4096];
__device__ float g_spart[256*64];
__device__ float g_G[4096];
__device__ float g_s[64];
__device__ __align__(16) float g_A[HID];
__device__ __align__(16) float g_B[HID];
__device__ float g_WfT[ZD*NBOND*ZD];    // transposed symmetrized bonds: [c][t*64+d]

// ---------------- K1: fused bond-symmetrize(transposed) + partial Gram/colsum ----------------
__global__ void k_prep_stats(const float* __restrict__ z, const float* __restrict__ bm) {
    __shared__ float zs[128*68];
    int tid = threadIdx.x;
    if (blockIdx.x >= 256) {          // 80 prep blocks
        int idx = (blockIdx.x - 256)*256 + tid;
        if (idx < ZD*NBOND*ZD) {
            int c = idx / 320, td = idx % 320;
            int t = td >> 6, d = td & 63;
            g_WfT[idx] = 0.5f*(bm[(t<<12)+(d<<6)+c] + bm[(t<<12)+(c<<6)+d]);
        }
        return;
    }
    int b = blockIdx.x;
    const float* zp = z + b*(128*64);
    for (int idx = tid; idx < 128*64; idx += 256)
        zs[(idx>>6)*68 + (idx&63)] = zp[idx];
    __syncthreads();

    int i0 = (tid & 15) << 2;
    int j0 = (tid >> 4) << 2;
    float acc[16];
#pragma unroll
    for (int k = 0; k < 16; k++) acc[k] = 0.f;
#pragma unroll 2
    for (int r = 0; r < 128; r++) {
        float zi[4], zj[4];
#pragma unroll
        for (int x = 0; x < 4; x++) { zi[x] = zs[r*68 + i0 + x]; zj[x] = zs[r*68 + j0 + x]; }
#pragma unroll
        for (int x = 0; x < 4; x++)
#pragma unroll
            for (int y = 0; y < 4; y++)
                acc[x*4+y] += zi[x]*zj[y];
    }
    float* gp = g_Gpart + b*4096;
#pragma unroll
    for (int k = 0; k < 16; k++) gp[tid*16 + k] = acc[k];

    if (tid < 64) {
        float s = 0.f;
        for (int r = 0; r < 128; r++) s += zs[r*68 + tid];
        g_spart[b*64 + tid] = s;
    }
}

// ---------------- K2: reduction, 4 threads per element ----------------
__global__ void k_reduce() {
    __shared__ float red[256];
    int t = threadIdx.x;
    int e = blockIdx.x*64 + (t & 63);
    int q = t >> 6;                     // quarter: partials q*64 .. q*64+63
    float s = 0.f;
    if (e < 4096) {
#pragma unroll 4
        for (int p = q*64; p < q*64 + 64; p++) s += g_Gpart[p*4096 + e];
    } else {
        int c = e - 4096;
#pragma unroll 4
        for (int p = q*64; p < q*64 + 64; p++) s += g_spart[p*64 + c];
    }
    red[t] = s;
    __syncthreads();
    if (t < 128) red[t] += red[t + 128];
    __syncthreads();
    if (t < 64) {
        float v = red[t] + red[t + 64];
        if (e < 4096) {
            int t16 = e >> 4, k = e & 15;
            int i = ((t16 & 15) << 2) + (k >> 2);
            int j = ((t16 >> 4) << 2) + (k & 3);
            g_G[i*64 + j] = v;
        } else {
            g_s[e - 4096] = v;
        }
    }
}

// ---------------- K3: analytic BN -> folded affine (4 j per block) ----------------
__global__ void k_finalize(const float* __restrict__ W1, const float* __restrict__ b1,
                           const float* __restrict__ gamma, const float* __restrict__ beta) {
    __shared__ float Gs[4096], ssh[64], Wc[4][64];
    __shared__ float red1[256], red2[256];
    int tid = threadIdx.x;
    for (int i = tid; i < 4096; i += 256) Gs[i] = g_G[i];
    if (tid < 64) ssh[tid] = g_s[tid];
    {
        int jj = tid >> 6, c = tid & 63;
        Wc[jj][c] = W1[c*HID + blockIdx.x*4 + jj];
    }
    __syncthreads();

    int d = tid & 63, jq = tid >> 6;
    float wdj = Wc[jq][d];
    float qv = 0.f;
#pragma unroll
    for (int c = 0; c < 64; c++) qv += Gs[d*64 + c] * Wc[jq][c];

    red1[tid] = ssh[d]*wdj;
    red2[tid] = qv*wdj;
    __syncthreads();
    for (int off = 32; off > 0; off >>= 1) {
        if (d < off) { red1[tid] += red1[tid+off]; red2[tid] += red2[tid+off]; }
        __syncthreads();
    }
    if (d == 0) {
        int j = blockIdx.x*4 + jq;
        const float invN = 1.f/(float)TOTA;
        float sw = red1[tid], wGw = red2[tid];
        float bj = b1[j];
        float m1 = sw*invN + bj;
        float m2 = (wGw + 2.f*bj*sw)*invN + bj*bj;
        float var = m2 - m1*m1;
        float A = rsqrtf(var + 1e-5f) * gamma[j];
        g_A[j] = A;
        g_B[j] = (bj - m1)*A + beta[j];
    }
}

// ---------------- K4: fused GEMM1+BN+GELU+GEMM2 ----------------
// 512 threads, 64 rows/block. smem: W1sh[64][256]=16384 | zdup[64][130]=8320 | W2t[10][260]=2600
__global__ __launch_bounds__(512, 2)
void k_atoms(const float* __restrict__ z, const float* __restrict__ W1,
             const float* __restrict__ W2, const float* __restrict__ b2,
             float* __restrict__ out) {
    extern __shared__ float sm[];
    float* W1sh = sm;                 // 16384
    float* zdup = sm + 16384;         // 8320  (dead after GEMM1)
    float* W2t  = sm + 24704;         // 2600
    int tid = threadIdx.x, b = blockIdx.x;
    const float* zp = z + b*(64*64);

    for (int i = tid; i < 16384; i += 512) W1sh[i] = W1[i];
    for (int i = tid; i < 4096;  i += 512) {
        int r = i >> 6, c = i & 63;
        float v = zp[i];
        *(float2*)&zdup[c*130 + 2*r] = make_float2(v, v);
    }
    for (int i = tid; i < 2560;  i += 512) { int jj = i/10, kk = i%10; W2t[kk*260 + jj] = W2[i]; }
    __syncthreads();

    int lane = tid & 31, w = tid >> 5;
    int r0 = w << 2, j0 = lane << 3;          // 4 rows x 8 cols (4 col-pairs)
    ull acc[4][4];
#pragma unroll
    for (int x = 0; x < 4; x++)
#pragma unroll
        for (int y = 0; y < 4; y++) acc[x][y] = 0ull;

#pragma unroll 2
    for (int c = 0; c < 64; c++) {
        ull zz[4];
#pragma unroll
        for (int x = 0; x < 4; x++) zz[x] = *(const ull*)&zdup[c*130 + 2*(r0+x)];
        ulonglong2 wA = *(const ulonglong2*)&W1sh[(c<<8) + j0];
        ulonglong2 wB = *(const ulonglong2*)&W1sh[(c<<8) + j0 + 4];
#pragma unroll
        for (int x = 0; x < 4; x++) {
            fma2(acc[x][0], zz[x], wA.x);
            fma2(acc[x][1], zz[x], wA.y);
            fma2(acc[x][2], zz[x], wB.x);
            fma2(acc[x][3], zz[x], wB.y);
        }
    }

    // folded BN + exact GELU
    float Av[8], Bv[8];
    { float4 a0 = *(const float4*)&g_A[j0], a1 = *(const float4*)&g_A[j0+4];
      float4 c0 = *(const float4*)&g_B[j0], c1 = *(const float4*)&g_B[j0+4];
      Av[0]=a0.x;Av[1]=a0.y;Av[2]=a0.z;Av[3]=a0.w;Av[4]=a1.x;Av[5]=a1.y;Av[6]=a1.z;Av[7]=a1.w;
      Bv[0]=c0.x;Bv[1]=c0.y;Bv[2]=c0.z;Bv[3]=c0.w;Bv[4]=c1.x;Bv[5]=c1.y;Bv[6]=c1.z;Bv[7]=c1.w; }
    float g[4][8];
#pragma unroll
    for (int x = 0; x < 4; x++)
#pragma unroll
        for (int y = 0; y < 4; y++) {
            float2 v = up(acc[x][y]);
            float t0 = v.x*Av[2*y]   + Bv[2*y];
            float t1 = v.y*Av[2*y+1] + Bv[2*y+1];
            g[x][2*y]   = 0.5f*t0*(1.f + erff(t0*0.70710678118654752f));
            g[x][2*y+1] = 0.5f*t1*(1.f + erff(t1*0.70710678118654752f));
        }

    __syncthreads();                          // W1sh/zdup dead
    float* gsh = sm;                          // g[64][260] (16640 < 24704: W2t safe)
#pragma unroll
    for (int x = 0; x < 4; x++)
#pragma unroll
        for (int y = 0; y < 4; y++)
            *(float2*)&gsh[(r0+x)*260 + j0 + 2*y] = make_float2(g[x][2*y], g[x][2*y+1]);
    __syncthreads();

    // GEMM2: 64x10 outputs
    for (int p = tid; p < 640; p += 512) {
        int r = p/10, k = p%10;
        const float4* gp4 = (const float4*)(gsh + r*260);
        const float4* wp4 = (const float4*)(W2t + k*260);
        float s = 0.f;
#pragma unroll
        for (int q = 0; q < 64; q++) {
            float4 a = gp4[q], ww = wp4[q];
            s += a.x*ww.x + a.y*ww.y + a.z*ww.z + a.w*ww.w;
        }
        out[(b*64 + r)*10 + k] = s + b2[k];
    }
}

// ---------------- K5: edges, 2 molecules/block, 512 threads ----------------
// smem: WfT[64][322]=20608 | zdup 2x[64][66]=8448 | Ysh 2x[320][34]=21760  (203264 B)
__global__ __launch_bounds__(512, 1)
void k_edges(const float* __restrict__ z, float* __restrict__ out) {
    extern __shared__ float sm[];
    float* WfTsh = sm;                       // 20608
    float* zdupB = sm + 20608;               // 2 x 4224
    float* YB    = sm + 29056;               // 2 x 10880
    int tid = threadIdx.x;
    int half = tid >> 8, t = tid & 255;
    int mol = blockIdx.x*2 + half;
    const float* zp = z + mol*2048;
    float* zdup = zdupB + half*4224;         // [c][2a], stride 66
    float* Yh   = YB   + half*10880;         // [td][a], stride 34

    for (int i = tid; i < 20480; i += 512) {
        int c = i / 320, td = i % 320;
        WfTsh[c*322 + td] = g_WfT[i];
    }
    for (int i = t; i < 2048; i += 256) {
        int a = i >> 6, c = i & 63;
        float v = zp[i];
        *(float2*)&zdup[c*66 + 2*a] = make_float2(v, v);
    }
    __syncthreads();

    // ---- Y phase: acc packed over q-pairs (WfT natural LDS.64), z splat from zdup ----
    {
        int p0 = (t >> 3) * 5;               // 5 q-pairs per thread
        int a0 = (t & 7) << 2;               // 4 atoms per thread
        ull acc[5][4];
#pragma unroll
        for (int y = 0; y < 5; y++)
#pragma unroll
            for (int k = 0; k < 4; k++) acc[y][k] = 0ull;

#pragma unroll 2
        for (int c = 0; c < 64; c++) {
            ull wq[5], za[4];
#pragma unroll
            for (int y = 0; y < 5; y++) wq[y] = *(const ull*)&WfTsh[c*322 + 2*(p0+y)];
#pragma unroll
            for (int k = 0; k < 4; k++) za[k] = *(const ull*)&zdup[c*66 + 2*(a0+k)];
#pragma unroll
            for (int y = 0; y < 5; y++)
#pragma unroll
                for (int k = 0; k < 4; k++) fma2(acc[y][k], wq[y], za[k]);
        }
#pragma unroll
        for (int y = 0; y < 5; y++)
#pragma unroll
            for (int k = 0; k < 4; k++) {
                float2 v = up(acc[y][k]);
                int q = 2*(p0+y);
                Yh[q*34     + a0 + k] = v.x;
                Yh[(q+1)*34 + a0 + k] = v.y;
            }
    }
    __syncthreads();

    // ---- edge phase: 2i x 2j per thread, packed over j-pair, all 5 types ----
    int i0 = (t >> 4) << 1, j0 = (t & 15) << 1;
    ull L[2][5];
#pragma unroll
    for (int x = 0; x < 2; x++)
#pragma unroll
        for (int tt = 0; tt < 5; tt++) L[x][tt] = 0ull;

#pragma unroll 2
    for (int d = 0; d < 64; d++) {
        ull zi0 = *(const ull*)&zdup[d*66 + 2*i0];
        ull zi1 = *(const ull*)&zdup[d*66 + 2*i0 + 2];
        ull yv[5];
#pragma unroll
        for (int tt = 0; tt < 5; tt++) yv[tt] = *(const ull*)&Yh[(tt*64 + d)*34 + j0];
#pragma unroll
        for (int tt = 0; tt < 5; tt++) { fma2(L[0][tt], zi0, yv[tt]); fma2(L[1][tt], zi1, yv[tt]); }
    }

    float* eout = out + ATOM_OUT + mol*(NEDGE*5);
#pragma unroll
    for (int x = 0; x < 2; x++) {
        float2 l0 = up(L[x][0]), l1 = up(L[x][1]), l2 = up(L[x][2]), l3 = up(L[x][3]), l4 = up(L[x][4]);
        int i = i0 + x;
#pragma unroll
        for (int y = 0; y < 2; y++) {
            int j = j0 + y;
            if (i < j) {
                float v0 = y ? l0.y : l0.x, v1 = y ? l1.y : l1.x, v2 = y ? l2.y : l2.x;
                float v3 = y ? l3.y : l3.x, v4 = y ? l4.y : l4.x;
                float m = fmaxf(fmaxf(fmaxf(v0, v1), fmaxf(v2, v3)), v4);
                float e0 = __expf(v0-m), e1 = __expf(v1-m), e2 = __expf(v2-m),
                      e3 = __expf(v3-m), e4 = __expf(v4-m);
                float inv = 1.f/(e0+e1+e2+e3+e4);
                int e = 31*i - (i*(i-1))/2 + (j - i - 1);
                float* dst = eout + e*5;
                dst[0] = e0*inv; dst[1] = e1*inv; dst[2] = e2*inv; dst[3] = e3*inv; dst[4] = e4*inv;
            }
        }
    }
}

// ---------------- launch ----------------
extern "C" void kernel_launch(void* const* d_in, const int* in_sizes, int n_in,
                              void* d_out, int out_size) {
    const float* z  = (const float*)d_in[0];
    const float* W1 = (const float*)d_in[1];
    const float* b1 = (const float*)d_in[2];
    const float* gm = (const float*)d_in[3];
    const float* bt = (const float*)d_in[4];
    const float* W2 = (const float*)d_in[5];
    const float* b2 = (const float*)d_in[6];
    const float* bm = (const float*)d_in[7];
    float* out = (float*)d_out;
    (void)in_sizes; (void)n_in; (void)out_size;

    const int SMEM_ATOMS = (16384 + 8320 + 2600) * 4;     // 109216 B
    const int SMEM_EDGES = (20608 + 8448 + 21760) * 4;    // 203264 B
    cudaFuncSetAttribute(k_atoms, cudaFuncAttributeMaxDynamicSharedMemorySize, SMEM_ATOMS);
    cudaFuncSetAttribute(k_edges, cudaFuncAttributeMaxDynamicSharedMemorySize, SMEM_EDGES);

    k_prep_stats<<<336, 256>>>(z, bm);
    k_reduce    <<<65,  256>>>();
    k_finalize  <<<64,  256>>>(W1, b1, gm, bt);
    k_atoms     <<<512, 512, SMEM_ATOMS>>>(z, W1, W2, b2, out);
    k_edges     <<<512, 512, SMEM_EDGES>>>(z, out);
}

// round 4
// speedup vs baseline: 1.0693x; 1.0320x over previous
#include <cuda_runtime.h>
#include <math.h>

#define NM     1024
#define NA     32
#define ZD     64
#define HID    256
#define NT     10
#define NBOND  5
#define NEDGE  496
#define TOTA   32768
#define ATOM_OUT (TOTA*NT)

typedef unsigned long long ull;

__device__ __forceinline__ ull pk(float lo, float hi) {
    ull r; asm("mov.b64 %0,{%1,%2};" : "=l"(r) : "f"(lo), "f"(hi)); return r;
}
__device__ __forceinline__ float2 up(ull v) {
    float2 r; asm("mov.b64 {%0,%1},%2;" : "=f"(r.x), "=f"(r.y) : "l"(v)); return r;
}
__device__ __forceinline__ void fma2(ull& d, ull a, ull b) {
    asm("fma.rn.f32x2 %0,%1,%2,%0;" : "+l"(d) : "l"(a), "l"(b));
}

// ---------------- device scratch ----------------
__device__ float g_Gpart[256*4096];
__device__ float g_spart[256*64];
__device__ float g_G[4096];
__device__ float g_s[64];
__device__ __align__(16) float g_A[HID];
__device__ __align__(16) float g_B[HID];
__device__ float g_WfT[ZD*NBOND*ZD];    // [c][t*64+d] transposed symmetrized bonds

// ---------------- K1: fused bond-symmetrize(T) + partial Gram/colsum ----------------
__global__ void k_prep_stats(const float* __restrict__ z, const float* __restrict__ bm) {
    __shared__ float zs[128*68];
    int tid = threadIdx.x;
    if (blockIdx.x >= 256) {          // 80 prep blocks
        int idx = (blockIdx.x - 256)*256 + tid;
        if (idx < ZD*NBOND*ZD) {
            int c = idx / 320, td = idx % 320;
            int t = td >> 6, d = td & 63;
            g_WfT[idx] = 0.5f*(bm[(t<<12)+(d<<6)+c] + bm[(t<<12)+(c<<6)+d]);
        }
        return;
    }
    int b = blockIdx.x;
    const float* zp = z + b*(128*64);
    for (int idx = tid; idx < 128*64; idx += 256)
        zs[(idx>>6)*68 + (idx&63)] = zp[idx];
    __syncthreads();

    int i0 = (tid & 15) << 2;
    int j0 = (tid >> 4) << 2;
    float acc[16];
#pragma unroll
    for (int k = 0; k < 16; k++) acc[k] = 0.f;
#pragma unroll 2
    for (int r = 0; r < 128; r++) {
        float zi[4], zj[4];
#pragma unroll
        for (int x = 0; x < 4; x++) { zi[x] = zs[r*68 + i0 + x]; zj[x] = zs[r*68 + j0 + x]; }
#pragma unroll
        for (int x = 0; x < 4; x++)
#pragma unroll
            for (int y = 0; y < 4; y++)
                acc[x*4+y] += zi[x]*zj[y];
    }
    float* gp = g_Gpart + b*4096;
#pragma unroll
    for (int k = 0; k < 16; k++) gp[tid*16 + k] = acc[k];

    if (tid < 64) {
        float s = 0.f;
        for (int r = 0; r < 128; r++) s += zs[r*68 + tid];
        g_spart[b*64 + tid] = s;
    }
}

// ---------------- K2: reduction, 4 threads per element ----------------
__global__ void k_reduce() {
    __shared__ float red[256];
    int t = threadIdx.x;
    int e = blockIdx.x*64 + (t & 63);
    int q = t >> 6;
    float s = 0.f;
    if (e < 4096) {
#pragma unroll 4
        for (int p = q*64; p < q*64 + 64; p++) s += g_Gpart[p*4096 + e];
    } else {
        int c = e - 4096;
#pragma unroll 4
        for (int p = q*64; p < q*64 + 64; p++) s += g_spart[p*64 + c];
    }
    red[t] = s;
    __syncthreads();
    if (t < 128) red[t] += red[t + 128];
    __syncthreads();
    if (t < 64) {
        float v = red[t] + red[t + 64];
        if (e < 4096) {
            int t16 = e >> 4, k = e & 15;
            int i = ((t16 & 15) << 2) + (k >> 2);
            int j = ((t16 >> 4) << 2) + (k & 3);
            g_G[i*64 + j] = v;
        } else {
            g_s[e - 4096] = v;
        }
    }
}

// ---------------- K3: analytic BN -> folded affine (4 j per block) ----------------
__global__ void k_finalize(const float* __restrict__ W1, const float* __restrict__ b1,
                           const float* __restrict__ gamma, const float* __restrict__ beta) {
    __shared__ float Gs[4096], ssh[64], Wc[4][64];
    __shared__ float red1[256], red2[256];
    int tid = threadIdx.x;
    for (int i = tid; i < 4096; i += 256) Gs[i] = g_G[i];
    if (tid < 64) ssh[tid] = g_s[tid];
    {
        int jj = tid >> 6, c = tid & 63;
        Wc[jj][c] = W1[c*HID + blockIdx.x*4 + jj];
    }
    __syncthreads();

    int d = tid & 63, jq = tid >> 6;
    float wdj = Wc[jq][d];
    float qv = 0.f;
#pragma unroll
    for (int c = 0; c < 64; c++) qv += Gs[d*64 + c] * Wc[jq][c];

    red1[tid] = ssh[d]*wdj;
    red2[tid] = qv*wdj;
    __syncthreads();
    for (int off = 32; off > 0; off >>= 1) {
        if (d < off) { red1[tid] += red1[tid+off]; red2[tid] += red2[tid+off]; }
        __syncthreads();
    }
    if (d == 0) {
        int j = blockIdx.x*4 + jq;
        const float invN = 1.f/(float)TOTA;
        float sw = red1[tid], wGw = red2[tid];
        float bj = b1[j];
        float m1 = sw*invN + bj;
        float m2 = (wGw + 2.f*bj*sw)*invN + bj*bj;
        float var = m2 - m1*m1;
        float A = rsqrtf(var + 1e-5f) * gamma[j];
        g_A[j] = A;
        g_B[j] = (bj - m1)*A + beta[j];
    }
}

// ---------------- K4: fused GEMM1+BN+GELU+GEMM2 ----------------
// 256 threads, 64 rows/block, 8x8 tile.
// smem: W1sh[64][256]=16384 | zdup[64][132]=8448 | W2sh[2560]  (27392 floats = 109568 B)
// after GEMM1, [0..16896) reused as gT[256][66]
__global__ __launch_bounds__(256, 2)
void k_atoms(const float* __restrict__ z, const float* __restrict__ W1,
             const float* __restrict__ W2, const float* __restrict__ b2,
             float* __restrict__ out) {
    extern __shared__ float sm[];
    float* W1sh = sm;                 // 16384
    float* zdup = sm + 16384;         // 8448
    float* W2sh = sm + 24832;         // 2560 (natural [j][k] layout)
    int tid = threadIdx.x, b = blockIdx.x;
    const float* zp = z + b*(64*64);

    for (int i = tid; i < 16384; i += 256) W1sh[i] = W1[i];
    for (int i = tid; i < 4096;  i += 256) {
        int r = i >> 6, c = i & 63;
        float v = zp[i];
        *(float2*)&zdup[c*132 + 2*r] = make_float2(v, v);
    }
    for (int i = tid; i < 2560;  i += 256) W2sh[i] = W2[i];
    __syncthreads();

    int lane = tid & 31, w = tid >> 5;
    int r0 = w << 3, j0 = lane << 3;          // 8 rows x 8 cols per thread
    ull acc[8][4];
#pragma unroll
    for (int x = 0; x < 8; x++)
#pragma unroll
        for (int y = 0; y < 4; y++) acc[x][y] = 0ull;

    const float* zc = zdup + 2*r0;            // warp-uniform (broadcast loads)
    const float* wc = W1sh + j0;
#pragma unroll 2
    for (int c = 0; c < 64; c++) {
        ulonglong2 z01 = *(const ulonglong2*)(zc);
        ulonglong2 z23 = *(const ulonglong2*)(zc + 4);
        ulonglong2 z45 = *(const ulonglong2*)(zc + 8);
        ulonglong2 z67 = *(const ulonglong2*)(zc + 12);
        ull zz[8] = { z01.x, z01.y, z23.x, z23.y, z45.x, z45.y, z67.x, z67.y };
        ulonglong2 wA = *(const ulonglong2*)(wc);
        ulonglong2 wB = *(const ulonglong2*)(wc + 4);
        ull wv[4] = { wA.x, wA.y, wB.x, wB.y };
#pragma unroll
        for (int x = 0; x < 8; x++) {
            fma2(acc[x][0], zz[x], wv[0]);
            fma2(acc[x][1], zz[x], wv[1]);
            fma2(acc[x][2], zz[x], wv[2]);
            fma2(acc[x][3], zz[x], wv[3]);
        }
        zc += 132; wc += 256;
    }

    // folded BN + exact GELU
    float Av[8], Bv[8];
    { float4 a0 = *(const float4*)&g_A[j0], a1 = *(const float4*)&g_A[j0+4];
      float4 c0 = *(const float4*)&g_B[j0], c1 = *(const float4*)&g_B[j0+4];
      Av[0]=a0.x;Av[1]=a0.y;Av[2]=a0.z;Av[3]=a0.w;Av[4]=a1.x;Av[5]=a1.y;Av[6]=a1.z;Av[7]=a1.w;
      Bv[0]=c0.x;Bv[1]=c0.y;Bv[2]=c0.z;Bv[3]=c0.w;Bv[4]=c1.x;Bv[5]=c1.y;Bv[6]=c1.z;Bv[7]=c1.w; }
    float g[8][8];
#pragma unroll
    for (int x = 0; x < 8; x++)
#pragma unroll
        for (int y = 0; y < 4; y++) {
            float2 v = up(acc[x][y]);
            float t0 = v.x*Av[2*y]   + Bv[2*y];
            float t1 = v.y*Av[2*y+1] + Bv[2*y+1];
            g[x][2*y]   = 0.5f*t0*(1.f + erff(t0*0.70710678118654752f));
            g[x][2*y+1] = 0.5f*t1*(1.f + erff(t1*0.70710678118654752f));
        }

    __syncthreads();                          // W1sh/zdup dead
    float* gT = sm;                           // gT[256 j][66 r]  (16896 < 24832)
#pragma unroll
    for (int y = 0; y < 8; y++)
#pragma unroll
        for (int x = 0; x < 8; x++)
            gT[(j0+y)*66 + r0+x] = g[x][y];
    __syncthreads();

    // GEMM2: 64 threads, row-pairs packed, 5 k each
    if (tid < 64) {
        int rp = tid & 31, kh = tid >> 5;     // k = kh*5 + kk
        ull a2[5] = {0ull,0ull,0ull,0ull,0ull};
        const float* gp = gT + 2*rp;
        const float* wp = W2sh + kh*5;
        for (int j = 0; j < 256; j++) {
            ull gpair = *(const ull*)(gp);
#pragma unroll
            for (int kk = 0; kk < 5; kk++) {
                float wv2 = wp[kk];
                fma2(a2[kk], gpair, pk(wv2, wv2));
            }
            gp += 66; wp += 10;
        }
        float* op = out + (b*64 + 2*rp)*10 + kh*5;
#pragma unroll
        for (int kk = 0; kk < 5; kk++) {
            float2 v = up(a2[kk]);
            float bb = b2[kh*5 + kk];
            op[kk]      = v.x + bb;
            op[10 + kk] = v.y + bb;
        }
    }
}

// ---------------- K5: edges, 2 molecules/block, 512 threads ----------------
// smem: WfT[64][322]=20608 | zdup 2x[64][68]=8704 | Yh 2x[320][40]=25600  (219648 B)
__global__ __launch_bounds__(512, 1)
void k_edges(const float* __restrict__ z, float* __restrict__ out) {
    extern __shared__ float sm[];
    float* WfTsh = sm;                       // 20608
    float* zdupB = sm + 20608;               // 2 x 4352
    float* YB    = sm + 29312;               // 2 x 12800
    int tid = threadIdx.x;

    for (int i = tid; i < 20480; i += 512) {
        int c = i / 320, td = i % 320;
        WfTsh[c*322 + td] = g_WfT[i];
    }
    {
        int half = tid >> 8, t = tid & 255;
        int mol = blockIdx.x*2 + half;
        const float* zp = z + mol*2048;
        float* zd = zdupB + half*4352;
        for (int i = t; i < 2048; i += 256) {
            int a = i >> 6, c = i & 63;
            float v = zp[i];
            *(float2*)&zd[c*68 + 2*a] = make_float2(v, v);
        }
    }
    __syncthreads();

    // ---- Y phase: lane -> 5 strided q-pairs (q=64y+2l), warp -> 4 atoms ----
    {
        int lane = tid & 31, w = tid >> 5;
        int molh = w >> 3, a0 = (w & 7) << 2;
        const float* zd = zdupB + molh*4352;
        float* Yh = YB + molh*12800;
        ull acc[5][4];
#pragma unroll
        for (int y = 0; y < 5; y++)
#pragma unroll
            for (int k = 0; k < 4; k++) acc[y][k] = 0ull;

        const float* wq = WfTsh + 2*lane;
        const float* za = zd + 2*a0;          // warp-uniform (broadcast)
#pragma unroll 2
        for (int c = 0; c < 64; c++) {
            ull wv[5];
#pragma unroll
            for (int y = 0; y < 5; y++) wv[y] = *(const ull*)(wq + 64*y);
            ulonglong2 z01 = *(const ulonglong2*)(za);
            ulonglong2 z23 = *(const ulonglong2*)(za + 4);
            ull zv[4] = { z01.x, z01.y, z23.x, z23.y };
#pragma unroll
            for (int y = 0; y < 5; y++) {
                fma2(acc[y][0], wv[y], zv[0]);
                fma2(acc[y][1], wv[y], zv[1]);
                fma2(acc[y][2], wv[y], zv[2]);
                fma2(acc[y][3], wv[y], zv[3]);
            }
            wq += 322; za += 68;
        }
#pragma unroll
        for (int y = 0; y < 5; y++) {
            int q = 64*y + 2*lane;
#pragma unroll
            for (int k = 0; k < 4; k++) {
                float2 v = up(acc[y][k]);
                Yh[q*40     + a0 + k] = v.x;
                Yh[(q+1)*40 + a0 + k] = v.y;
            }
        }
    }
    __syncthreads();

    // ---- edge phase: thread = 1 i x 4 j (2 j-pairs), all 5 types ----
    {
        int half = tid >> 8, t = tid & 255;
        int mol = blockIdx.x*2 + half;
        const float* zd = zdupB + half*4352;
        const float* Yh = YB + half*12800;
        int i = t >> 3, j0 = (t & 7) << 2;
        ull L[2][5];
#pragma unroll
        for (int x = 0; x < 2; x++)
#pragma unroll
            for (int tt = 0; tt < 5; tt++) L[x][tt] = 0ull;

        const float* zi_p = zd + 2*i;
        const float* yv_p = Yh + j0;
#pragma unroll 2
        for (int d = 0; d < 64; d++) {
            ull zi = *(const ull*)(zi_p);
#pragma unroll
            for (int tt = 0; tt < 5; tt++) {
                ulonglong2 yv = *(const ulonglong2*)(yv_p + tt*2560);  // (tt*64)*40
                fma2(L[0][tt], zi, yv.x);
                fma2(L[1][tt], zi, yv.y);
            }
            zi_p += 68; yv_p += 40;
        }

        float2 U[2][5];
#pragma unroll
        for (int x = 0; x < 2; x++)
#pragma unroll
            for (int tt = 0; tt < 5; tt++) U[x][tt] = up(L[x][tt]);

        float* eout = out + ATOM_OUT + mol*(NEDGE*5);
#pragma unroll
        for (int jj = 0; jj < 4; jj++) {
            int j = j0 + jj;
            if (i < j) {
                int jp = jj >> 1;
                float v0 = (jj&1) ? U[jp][0].y : U[jp][0].x;
                float v1 = (jj&1) ? U[jp][1].y : U[jp][1].x;
                float v2 = (jj&1) ? U[jp][2].y : U[jp][2].x;
                float v3 = (jj&1) ? U[jp][3].y : U[jp][3].x;
                float v4 = (jj&1) ? U[jp][4].y : U[jp][4].x;
                float m = fmaxf(fmaxf(fmaxf(v0, v1), fmaxf(v2, v3)), v4);
                float e0 = __expf(v0-m), e1 = __expf(v1-m), e2 = __expf(v2-m),
                      e3 = __expf(v3-m), e4 = __expf(v4-m);
                float inv = 1.f/(e0+e1+e2+e3+e4);
                int e = 31*i - (i*(i-1))/2 + (j - i - 1);
                float* dst = eout + e*5;
                dst[0] = e0*inv; dst[1] = e1*inv; dst[2] = e2*inv;
                dst[3] = e3*inv; dst[4] = e4*inv;
            }
        }
    }
}

// ---------------- launch ----------------
extern "C" void kernel_launch(void* const* d_in, const int* in_sizes, int n_in,
                              void* d_out, int out_size) {
    const float* z  = (const float*)d_in[0];
    const float* W1 = (const float*)d_in[1];
    const float* b1 = (const float*)d_in[2];
    const float* gm = (const float*)d_in[3];
    const float* bt = (const float*)d_in[4];
    const float* W2 = (const float*)d_in[5];
    const float* b2 = (const float*)d_in[6];
    const float* bm = (const float*)d_in[7];
    float* out = (float*)d_out;
    (void)in_sizes; (void)n_in; (void)out_size;

    const int SMEM_ATOMS = (16384 + 8448 + 2560) * 4;     // 109568 B
    const int SMEM_EDGES = (20608 + 8704 + 25600) * 4;    // 219648 B
    cudaFuncSetAttribute(k_atoms, cudaFuncAttributeMaxDynamicSharedMemorySize, SMEM_ATOMS);
    cudaFuncSetAttribute(k_edges, cudaFuncAttributeMaxDynamicSharedMemorySize, SMEM_EDGES);

    k_prep_stats<<<336, 256>>>(z, bm);
    k_reduce    <<<65,  256>>>();
    k_finalize  <<<64,  256>>>(W1, b1, gm, bt);
    k_atoms     <<<512, 256, SMEM_ATOMS>>>(z, W1, W2, b2, out);
    k_edges     <<<512, 512, SMEM_EDGES>>>(z, out);
}

// round 6
// speedup vs baseline: 1.1498x; 1.0753x over previous
#include <cuda_runtime.h>
#include <cuda_bf16.h>
#include <math.h>
#include <stdint.h>

#define NM     1024
#define NA     32
#define ZD     64
#define HID    256
#define NT     10
#define NBOND  5
#define NEDGE  496
#define TOTA   32768
#define ATOM_OUT (TOTA*NT)

typedef unsigned long long ull;

__device__ __forceinline__ ull pk(float lo, float hi) {
    ull r; asm("mov.b64 %0,{%1,%2};" : "=l"(r) : "f"(lo), "f"(hi)); return r;
}
__device__ __forceinline__ float2 up(ull v) {
    float2 r; asm("mov.b64 {%0,%1},%2;" : "=f"(r.x), "=f"(r.y) : "l"(v)); return r;
}
__device__ __forceinline__ void fma2(ull& d, ull a, ull b) {
    asm("fma.rn.f32x2 %0,%1,%2,%0;" : "+l"(d) : "l"(a), "l"(b));
}
__device__ __forceinline__ uint32_t smem_u32(const void* p) {
    uint32_t a;
    asm("{ .reg .u64 t; cvta.to.shared.u64 t, %1; cvt.u32.u64 %0, t; }" : "=r"(a) : "l"(p));
    return a;
}
// ---- Ampere-class tensor path (plain sm_80 PTX, no 'a'-gated features) ----
__device__ __forceinline__ void ldmA(uint32_t* r, uint32_t a) {
    asm volatile("ldmatrix.sync.aligned.m8n8.x4.shared.b16 {%0,%1,%2,%3}, [%4];"
                 : "=r"(r[0]), "=r"(r[1]), "=r"(r[2]), "=r"(r[3]) : "r"(a));
}
__device__ __forceinline__ void ldmBt(uint32_t* r, uint32_t a) {
    asm volatile("ldmatrix.sync.aligned.m8n8.x4.trans.shared.b16 {%0,%1,%2,%3}, [%4];"
                 : "=r"(r[0]), "=r"(r[1]), "=r"(r[2]), "=r"(r[3]) : "r"(a));
}
__device__ __forceinline__ void mma_bf16(float* c, const uint32_t* a, uint32_t b0, uint32_t b1) {
    asm volatile("mma.sync.aligned.m16n8k16.row.col.f32.bf16.bf16.f32 "
                 "{%0,%1,%2,%3},{%4,%5,%6,%7},{%8,%9},{%0,%1,%2,%3};"
                 : "+f"(c[0]), "+f"(c[1]), "+f"(c[2]), "+f"(c[3])
                 : "r"(a[0]), "r"(a[1]), "r"(a[2]), "r"(a[3]), "r"(b0), "r"(b1));
}
__device__ __forceinline__ float gelu_exact(float t) {
    return 0.5f*t*(1.f + erff(t*0.70710678118654752f));
}

// ---------------- device scratch ----------------
__device__ float g_Gpart[256*4096];
__device__ float g_spart[256*64];
__device__ float g_G[4096];
__device__ float g_s[64];
__device__ __align__(16) float g_A[HID];
__device__ __align__(16) float g_B[HID];
__device__ float g_WfT[ZD*NBOND*ZD];    // [c][t*64+d] transposed symmetrized bonds

// ---------------- K1: fused bond-symmetrize(T) + partial Gram/colsum ----------------
__global__ void k_prep_stats(const float* __restrict__ z, const float* __restrict__ bm) {
    __shared__ float zs[128*68];
    int tid = threadIdx.x;
    if (blockIdx.x >= 256) {
        int idx = (blockIdx.x - 256)*256 + tid;
        if (idx < ZD*NBOND*ZD) {
            int c = idx / 320, td = idx % 320;
            int t = td >> 6, d = td & 63;
            g_WfT[idx] = 0.5f*(bm[(t<<12)+(d<<6)+c] + bm[(t<<12)+(c<<6)+d]);
        }
        return;
    }
    int b = blockIdx.x;
    const float* zp = z + b*(128*64);
    for (int idx = tid; idx < 128*64; idx += 256)
        zs[(idx>>6)*68 + (idx&63)] = zp[idx];
    __syncthreads();

    int i0 = (tid & 15) << 2;
    int j0 = (tid >> 4) << 2;
    float acc[16];
#pragma unroll
    for (int k = 0; k < 16; k++) acc[k] = 0.f;
#pragma unroll 2
    for (int r = 0; r < 128; r++) {
        float zi[4], zj[4];
#pragma unroll
        for (int x = 0; x < 4; x++) { zi[x] = zs[r*68 + i0 + x]; zj[x] = zs[r*68 + j0 + x]; }
#pragma unroll
        for (int x = 0; x < 4; x++)
#pragma unroll
            for (int y = 0; y < 4; y++)
                acc[x*4+y] += zi[x]*zj[y];
    }
    float* gp = g_Gpart + b*4096;
#pragma unroll
    for (int k = 0; k < 16; k++) gp[tid*16 + k] = acc[k];

    if (tid < 64) {
        float s = 0.f;
        for (int r = 0; r < 128; r++) s += zs[r*68 + tid];
        g_spart[b*64 + tid] = s;
    }
}

// ---------------- K2: reduction ----------------
__global__ void k_reduce() {
    __shared__ float red[256];
    int t = threadIdx.x;
    int e = blockIdx.x*64 + (t & 63);
    int q = t >> 6;
    float s = 0.f;
    if (e < 4096) {
#pragma unroll 4
        for (int p = q*64; p < q*64 + 64; p++) s += g_Gpart[p*4096 + e];
    } else {
        int c = e - 4096;
#pragma unroll 4
        for (int p = q*64; p < q*64 + 64; p++) s += g_spart[p*64 + c];
    }
    red[t] = s;
    __syncthreads();
    if (t < 128) red[t] += red[t + 128];
    __syncthreads();
    if (t < 64) {
        float v = red[t] + red[t + 64];
        if (e < 4096) {
            int t16 = e >> 4, k = e & 15;
            int i = ((t16 & 15) << 2) + (k >> 2);
            int j = ((t16 >> 4) << 2) + (k & 3);
            g_G[i*64 + j] = v;
        } else {
            g_s[e - 4096] = v;
        }
    }
}

// ---------------- K3: analytic BN -> folded affine ----------------
__global__ void k_finalize(const float* __restrict__ W1, const float* __restrict__ b1,
                           const float* __restrict__ gamma, const float* __restrict__ beta) {
    __shared__ float Gs[4096], ssh[64], Wc[4][64];
    __shared__ float red1[256], red2[256];
    int tid = threadIdx.x;
    for (int i = tid; i < 4096; i += 256) Gs[i] = g_G[i];
    if (tid < 64) ssh[tid] = g_s[tid];
    {
        int jj = tid >> 6, c = tid & 63;
        Wc[jj][c] = W1[c*HID + blockIdx.x*4 + jj];
    }
    __syncthreads();

    int d = tid & 63, jq = tid >> 6;
    float wdj = Wc[jq][d];
    float qv = 0.f;
#pragma unroll
    for (int c = 0; c < 64; c++) qv += Gs[d*64 + c] * Wc[jq][c];

    red1[tid] = ssh[d]*wdj;
    red2[tid] = qv*wdj;
    __syncthreads();
    for (int off = 32; off > 0; off >>= 1) {
        if (d < off) { red1[tid] += red1[tid+off]; red2[tid] += red2[tid+off]; }
        __syncthreads();
    }
    if (d == 0) {
        int j = blockIdx.x*4 + jq;
        const float invN = 1.f/(float)TOTA;
        float sw = red1[tid], wGw = red2[tid];
        float bj = b1[j];
        float m1 = sw*invN + bj;
        float m2 = (wGw + 2.f*bj*sw)*invN + bj*bj;
        float var = m2 - m1*m1;
        float A = rsqrtf(var + 1e-5f) * gamma[j];
        g_A[j] = A;
        g_B[j] = (bj - m1)*A + beta[j];
    }
}

// ---------------- K4: mma.sync bf16-split GEMM1 + BN + GELU + f32x2 GEMM2 ----------------
// 128 rows/block, 256 blocks, 512 threads (16 warps).
// smem bytes:
//   A halves [128 m][200 k-pad]  :      0 .. 51200      (K'=192 = [z_hi | z_hi | z_lo])
//   B halves [192 k][264 n-pad]  :  51200 .. 152576     (k-rows = [W_hi | W_lo | W_hi])
//   W2sh 2560 f32                : 152576 .. 162816
//   gA 256 f32                   : 162816   gB: 163840
// epilogue reuses [0..135168) as hT[256 j][132 r] f32
#define KA_A    0u
#define KA_B    51200u
#define KA_W2   152576u
#define KA_GA   162816u
#define KA_GB   163840u
#define KA_TOT  164864

__global__ __launch_bounds__(512, 1)
void k_atoms_mma(const float* __restrict__ z, const float* __restrict__ W1,
                 const float* __restrict__ W2, const float* __restrict__ b2,
                 float* __restrict__ out) {
    extern __shared__ char smem[];
    uint32_t sb = smem_u32(smem);
    int tid = threadIdx.x, b = blockIdx.x;
    int lane = tid & 31, w = tid >> 5;

    // ---- stage A: z hi/lo split, k-blocks [hi, hi, lo], stride 200 halves ----
    const float* zp = z + (size_t)b*(128*64);
    for (int it = tid; it < 4096; it += 512) {
        int m = it >> 5, c = (it & 31)*2;
        float2 v = *(const float2*)&zp[m*64 + c];
        __nv_bfloat16 h0 = __float2bfloat16(v.x), h1 = __float2bfloat16(v.y);
        __nv_bfloat16 l0 = __float2bfloat16(v.x - __bfloat162float(h0));
        __nv_bfloat16 l1 = __float2bfloat16(v.y - __bfloat162float(h1));
        __nv_bfloat162 hp(h0, h1), lp(l0, l1);
        uint32_t hh = *reinterpret_cast<uint32_t*>(&hp);
        uint32_t ll = *reinterpret_cast<uint32_t*>(&lp);
        char* base = smem + KA_A + m*400 + c*2;
        *(uint32_t*)(base)       = hh;      // k = c
        *(uint32_t*)(base + 128) = hh;      // k = 64 + c
        *(uint32_t*)(base + 256) = ll;      // k = 128 + c
    }
    // ---- stage B: W1 hi/lo split, k-rows [hi, lo, hi], stride 264 halves ----
    for (int it = tid; it < 8192; it += 512) {
        int j = (it & 127)*2, c = it >> 7;
        float2 wv = *(const float2*)&W1[c*256 + j];
        __nv_bfloat16 h0 = __float2bfloat16(wv.x), h1 = __float2bfloat16(wv.y);
        __nv_bfloat16 l0 = __float2bfloat16(wv.x - __bfloat162float(h0));
        __nv_bfloat16 l1 = __float2bfloat16(wv.y - __bfloat162float(h1));
        __nv_bfloat162 hp(h0, h1), lp(l0, l1);
        uint32_t hh = *reinterpret_cast<uint32_t*>(&hp);
        uint32_t ll = *reinterpret_cast<uint32_t*>(&lp);
        char* base = smem + KA_B + c*528 + j*2;
        *(uint32_t*)(base)           = hh;   // row c      (W_hi)
        *(uint32_t*)(base + 33792)   = ll;   // row 64+c   (W_lo)  64*528
        *(uint32_t*)(base + 67584)   = hh;   // row 128+c  (W_hi)  128*528
    }
    float* W2sh = (float*)(smem + KA_W2);
    float* gAs  = (float*)(smem + KA_GA);
    float* gBs  = (float*)(smem + KA_GB);
    for (int i = tid; i < 2560; i += 512) W2sh[i] = W2[i];
    if (tid < 256) { gAs[tid] = g_A[tid]; gBs[tid] = g_B[tid]; }
    __syncthreads();

    // ---- mainloop: warp = 16 rows x 128 cols; 12 k16-steps ----
    int mt = w & 7, nh = w >> 3;
    float acc[16][4];
#pragma unroll
    for (int i = 0; i < 16; i++)
#pragma unroll
        for (int x = 0; x < 4; x++) acc[i][x] = 0.f;

    uint32_t aaddr = sb + KA_A + (uint32_t)((mt*16 + (lane & 15))*400 + (lane >> 4)*16);
    uint32_t baddr = sb + KA_B + (uint32_t)((lane & 15)*528 + (nh*128 + (lane >> 4)*8)*2);
#pragma unroll
    for (int s = 0; s < 12; s++) {
        uint32_t ar[4];
        ldmA(ar, aaddr + s*32);
        uint32_t bb = baddr + s*16*528;
#pragma unroll
        for (int i = 0; i < 8; i++) {
            uint32_t br[4];
            ldmBt(br, bb + i*32);
            mma_bf16(acc[2*i],     ar, br[0], br[1]);
            mma_bf16(acc[2*i + 1], ar, br[2], br[3]);
        }
    }
    __syncthreads();                     // all ldmatrix done; A/B regions now dead

    // ---- epilogue: BN + GELU on C-frags -> hT[j][r] ----
    float* hT = (float*)smem;            // [256][132]
    int g = lane >> 2, tig = lane & 3;
    int r1 = mt*16 + g, r2 = r1 + 8;
#pragma unroll
    for (int a = 0; a < 16; a++) {
        int j0 = nh*128 + a*8 + 2*tig;
        float2 A2 = *(float2*)&gAs[j0];
        float2 B2 = *(float2*)&gBs[j0];
        hT[j0*132 + r1]     = gelu_exact(acc[a][0]*A2.x + B2.x);
        hT[(j0+1)*132 + r1] = gelu_exact(acc[a][1]*A2.y + B2.y);
        hT[j0*132 + r2]     = gelu_exact(acc[a][2]*A2.x + B2.x);
        hT[(j0+1)*132 + r2] = gelu_exact(acc[a][3]*A2.y + B2.y);
    }
    __syncthreads();

    // ---- GEMM2: 1280 outputs (64 row-pairs x 10), f32x2 ----
    for (int it = tid; it < 640; it += 512) {
        int rp = it & 63, k = it >> 6;
        ull a2 = 0ull;
        const float* hp = hT + 2*rp;
        const float* wp = W2sh + k;
#pragma unroll 4
        for (int j = 0; j < 256; j++) {
            ull g2 = *(const ull*)(hp);
            float wv = *wp;
            fma2(a2, g2, pk(wv, wv));
            hp += 132; wp += 10;
        }
        float2 vv = up(a2);
        float bb = b2[k];
        out[((size_t)b*128 + 2*rp)*10 + k]     = vv.x + bb;
        out[((size_t)b*128 + 2*rp + 1)*10 + k] = vv.y + bb;
    }
}

// ---------------- K5: edges, 2 molecules/block, 512 threads (unchanged, known-good) ----------------
__global__ __launch_bounds__(512, 1)
void k_edges(const float* __restrict__ z, float* __restrict__ out) {
    extern __shared__ float sm[];
    float* WfTsh = sm;                       // 20608
    float* zdupB = sm + 20608;               // 2 x 4352
    float* YB    = sm + 29312;               // 2 x 12800
    int tid = threadIdx.x;

    for (int i = tid; i < 20480; i += 512) {
        int c = i / 320, td = i % 320;
        WfTsh[c*322 + td] = g_WfT[i];
    }
    {
        int half = tid >> 8, t = tid & 255;
        int mol = blockIdx.x*2 + half;
        const float* zp = z + mol*2048;
        float* zd = zdupB + half*4352;
        for (int i = t; i < 2048; i += 256) {
            int a = i >> 6, c = i & 63;
            float v = zp[i];
            *(float2*)&zd[c*68 + 2*a] = make_float2(v, v);
        }
    }
    __syncthreads();

    {
        int lane = tid & 31, w = tid >> 5;
        int molh = w >> 3, a0 = (w & 7) << 2;
        const float* zd = zdupB + molh*4352;
        float* Yh = YB + molh*12800;
        ull acc[5][4];
#pragma unroll
        for (int y = 0; y < 5; y++)
#pragma unroll
            for (int k = 0; k < 4; k++) acc[y][k] = 0ull;

        const float* wq = WfTsh + 2*lane;
        const float* za = zd + 2*a0;
#pragma unroll 2
        for (int c = 0; c < 64; c++) {
            ull wv[5];
#pragma unroll
            for (int y = 0; y < 5; y++) wv[y] = *(const ull*)(wq + 64*y);
            ulonglong2 z01 = *(const ulonglong2*)(za);
            ulonglong2 z23 = *(const ulonglong2*)(za + 4);
            ull zv[4] = { z01.x, z01.y, z23.x, z23.y };
#pragma unroll
            for (int y = 0; y < 5; y++) {
                fma2(acc[y][0], wv[y], zv[0]);
                fma2(acc[y][1], wv[y], zv[1]);
                fma2(acc[y][2], wv[y], zv[2]);
                fma2(acc[y][3], wv[y], zv[3]);
            }
            wq += 322; za += 68;
        }
#pragma unroll
        for (int y = 0; y < 5; y++) {
            int q = 64*y + 2*lane;
#pragma unroll
            for (int k = 0; k < 4; k++) {
                float2 v = up(acc[y][k]);
                Yh[q*40     + a0 + k] = v.x;
                Yh[(q+1)*40 + a0 + k] = v.y;
            }
        }
    }
    __syncthreads();

    {
        int half = tid >> 8, t = tid & 255;
        int mol = blockIdx.x*2 + half;
        const float* zd = zdupB + half*4352;
        const float* Yh = YB + half*12800;
        int i = t >> 3, j0 = (t & 7) << 2;
        ull L[2][5];
#pragma unroll
        for (int x = 0; x < 2; x++)
#pragma unroll
            for (int tt = 0; tt < 5; tt++) L[x][tt] = 0ull;

        const float* zi_p = zd + 2*i;
        const float* yv_p = Yh + j0;
#pragma unroll 2
        for (int d = 0; d < 64; d++) {
            ull zi = *(const ull*)(zi_p);
#pragma unroll
            for (int tt = 0; tt < 5; tt++) {
                ulonglong2 yv = *(const ulonglong2*)(yv_p + tt*2560);
                fma2(L[0][tt], zi, yv.x);
                fma2(L[1][tt], zi, yv.y);
            }
            zi_p += 68; yv_p += 40;
        }

        float2 U[2][5];
#pragma unroll
        for (int x = 0; x < 2; x++)
#pragma unroll
            for (int tt = 0; tt < 5; tt++) U[x][tt] = up(L[x][tt]);

        float* eout = out + ATOM_OUT + mol*(NEDGE*5);
#pragma unroll
        for (int jj = 0; jj < 4; jj++) {
            int j = j0 + jj;
            if (i < j) {
                int jp = jj >> 1;
                float v0 = (jj&1) ? U[jp][0].y : U[jp][0].x;
                float v1 = (jj&1) ? U[jp][1].y : U[jp][1].x;
                float v2 = (jj&1) ? U[jp][2].y : U[jp][2].x;
                float v3 = (jj&1) ? U[jp][3].y : U[jp][3].x;
                float v4 = (jj&1) ? U[jp][4].y : U[jp][4].x;
                float m = fmaxf(fmaxf(fmaxf(v0, v1), fmaxf(v2, v3)), v4);
                float e0 = __expf(v0-m), e1 = __expf(v1-m), e2 = __expf(v2-m),
                      e3 = __expf(v3-m), e4 = __expf(v4-m);
                float inv = 1.f/(e0+e1+e2+e3+e4);
                int e = 31*i - (i*(i-1))/2 + (j - i - 1);
                float* dst = eout + e*5;
                dst[0] = e0*inv; dst[1] = e1*inv; dst[2] = e2*inv;
                dst[3] = e3*inv; dst[4] = e4*inv;
            }
        }
    }
}

// ---------------- launch ----------------
extern "C" void kernel_launch(void* const* d_in, const int* in_sizes, int n_in,
                              void* d_out, int out_size) {
    const float* z  = (const float*)d_in[0];
    const float* W1 = (const float*)d_in[1];
    const float* b1 = (const float*)d_in[2];
    const float* gm = (const float*)d_in[3];
    const float* bt = (const float*)d_in[4];
    const float* W2 = (const float*)d_in[5];
    const float* b2 = (const float*)d_in[6];
    const float* bm = (const float*)d_in[7];
    float* out = (float*)d_out;
    (void)in_sizes; (void)n_in; (void)out_size;

    const int SMEM_EDGES = (20608 + 8704 + 25600) * 4;    // 219648 B
    cudaFuncSetAttribute(k_atoms_mma, cudaFuncAttributeMaxDynamicSharedMemorySize, KA_TOT);
    cudaFuncSetAttribute(k_edges, cudaFuncAttributeMaxDynamicSharedMemorySize, SMEM_EDGES);

    k_prep_stats<<<336, 256>>>(z, bm);
    k_reduce    <<<65,  256>>>();
    k_finalize  <<<64,  256>>>(W1, b1, gm, bt);
    k_atoms_mma <<<256, 512, KA_TOT>>>(z, W1, W2, b2, out);
    k_edges     <<<512, 512, SMEM_EDGES>>>(z, out);
}

// round 7
// speedup vs baseline: 1.5204x; 1.3223x over previous
#include <cuda_runtime.h>
#include <cuda_bf16.h>
#include <math.h>
#include <stdint.h>

#define NM     1024
#define NA     32
#define ZD     64
#define HID    256
#define NT     10
#define NBOND  5
#define NEDGE  496
#define TOTA   32768
#define ATOM_OUT (TOTA*NT)

typedef unsigned long long ull;

__device__ __forceinline__ ull pk(float lo, float hi) {
    ull r; asm("mov.b64 %0,{%1,%2};" : "=l"(r) : "f"(lo), "f"(hi)); return r;
}
__device__ __forceinline__ float2 up(ull v) {
    float2 r; asm("mov.b64 {%0,%1},%2;" : "=f"(r.x), "=f"(r.y) : "l"(v)); return r;
}
__device__ __forceinline__ void fma2(ull& d, ull a, ull b) {
    asm("fma.rn.f32x2 %0,%1,%2,%0;" : "+l"(d) : "l"(a), "l"(b));
}
__device__ __forceinline__ uint32_t smem_u32(const void* p) {
    uint32_t a;
    asm("{ .reg .u64 t; cvta.to.shared.u64 t, %1; cvt.u32.u64 %0, t; }" : "=r"(a) : "l"(p));
    return a;
}
// ---- Ampere-class tensor path (plain sm_80 PTX) ----
__device__ __forceinline__ void ldmA(uint32_t* r, uint32_t a) {
    asm volatile("ldmatrix.sync.aligned.m8n8.x4.shared.b16 {%0,%1,%2,%3}, [%4];"
                 : "=r"(r[0]), "=r"(r[1]), "=r"(r[2]), "=r"(r[3]) : "r"(a));
}
__device__ __forceinline__ void ldmBt(uint32_t* r, uint32_t a) {
    asm volatile("ldmatrix.sync.aligned.m8n8.x4.trans.shared.b16 {%0,%1,%2,%3}, [%4];"
                 : "=r"(r[0]), "=r"(r[1]), "=r"(r[2]), "=r"(r[3]) : "r"(a));
}
__device__ __forceinline__ void ldmBt2(uint32_t* r, uint32_t a) {
    asm volatile("ldmatrix.sync.aligned.m8n8.x2.trans.shared.b16 {%0,%1}, [%2];"
                 : "=r"(r[0]), "=r"(r[1]) : "r"(a));
}
__device__ __forceinline__ void mma_bf16(float* c, const uint32_t* a, uint32_t b0, uint32_t b1) {
    asm volatile("mma.sync.aligned.m16n8k16.row.col.f32.bf16.bf16.f32 "
                 "{%0,%1,%2,%3},{%4,%5,%6,%7},{%8,%9},{%0,%1,%2,%3};"
                 : "+f"(c[0]), "+f"(c[1]), "+f"(c[2]), "+f"(c[3])
                 : "r"(a[0]), "r"(a[1]), "r"(a[2]), "r"(a[3]), "r"(b0), "r"(b1));
}
__device__ __forceinline__ float gelu_exact(float t) {
    return 0.5f*t*(1.f + erff(t*0.70710678118654752f));
}

// ---------------- device scratch ----------------
__device__ float g_Gpart[256*4096];
__device__ float g_spart[256*64];
__device__ float g_G[4096];
__device__ float g_s[64];
__device__ __align__(16) float g_A[HID];
__device__ __align__(16) float g_B[HID];
__device__ __nv_bfloat16 g_Wf_hi[NBOND*ZD*ZD];    // [td][c] symmetrized, hi
__device__ __nv_bfloat16 g_Wf_lo[NBOND*ZD*ZD];    // [td][c] lo residual
__device__ __nv_bfloat16 g_z_hi[TOTA*ZD];         // z hi   (4 MB)
__device__ __nv_bfloat16 g_z_lo[TOTA*ZD];         // z lo   (4 MB)

// ---------------- K1: fused prep (Wf split, z split) + partial Gram/colsum ----------------
__global__ void k_prep_stats(const float* __restrict__ z, const float* __restrict__ bm) {
    __shared__ float zs[128*68];
    int tid = threadIdx.x;
    int b = blockIdx.x;
    if (b >= 336) {                       // 512 z-split blocks
        size_t base = ((size_t)(b - 336)*256 + tid)*16;
#pragma unroll
        for (int r = 0; r < 4; r++) {
            float4 v = *(const float4*)(z + base + r*4);
            __nv_bfloat16 h0=__float2bfloat16(v.x), h1=__float2bfloat16(v.y),
                          h2=__float2bfloat16(v.z), h3=__float2bfloat16(v.w);
            __nv_bfloat16 l0=__float2bfloat16(v.x-__bfloat162float(h0));
            __nv_bfloat16 l1=__float2bfloat16(v.y-__bfloat162float(h1));
            __nv_bfloat16 l2=__float2bfloat16(v.z-__bfloat162float(h2));
            __nv_bfloat16 l3=__float2bfloat16(v.w-__bfloat162float(h3));
            __nv_bfloat162 hp0(h0,h1), hp1(h2,h3), lp0(l0,l1), lp1(l2,l3);
            uint2 hh = make_uint2(*(uint32_t*)&hp0, *(uint32_t*)&hp1);
            uint2 ll = make_uint2(*(uint32_t*)&lp0, *(uint32_t*)&lp1);
            *(uint2*)&g_z_hi[base + r*4] = hh;
            *(uint2*)&g_z_lo[base + r*4] = ll;
        }
        return;
    }
    if (b >= 256) {                       // 80 Wf-prep blocks
        int idx = (b - 256)*256 + tid;    // exactly 20480
        int td = idx >> 6, c = idx & 63;
        int t = td >> 6, d = td & 63;
        float val = 0.5f*(bm[(t<<12)+(d<<6)+c] + bm[(t<<12)+(c<<6)+d]);
        __nv_bfloat16 h = __float2bfloat16(val);
        g_Wf_hi[idx] = h;
        g_Wf_lo[idx] = __float2bfloat16(val - __bfloat162float(h));
        return;
    }
    const float* zp = z + b*(128*64);
    for (int idx = tid; idx < 128*64; idx += 256)
        zs[(idx>>6)*68 + (idx&63)] = zp[idx];
    __syncthreads();

    int i0 = (tid & 15) << 2;
    int j0 = (tid >> 4) << 2;
    float acc[16];
#pragma unroll
    for (int k = 0; k < 16; k++) acc[k] = 0.f;
#pragma unroll 2
    for (int r = 0; r < 128; r++) {
        float zi[4], zj[4];
#pragma unroll
        for (int x = 0; x < 4; x++) { zi[x] = zs[r*68 + i0 + x]; zj[x] = zs[r*68 + j0 + x]; }
#pragma unroll
        for (int x = 0; x < 4; x++)
#pragma unroll
            for (int y = 0; y < 4; y++)
                acc[x*4+y] += zi[x]*zj[y];
    }
    float* gp = g_Gpart + b*4096;
#pragma unroll
    for (int k = 0; k < 16; k++) gp[tid*16 + k] = acc[k];

    if (tid < 64) {
        float s = 0.f;
        for (int r = 0; r < 128; r++) s += zs[r*68 + tid];
        g_spart[b*64 + tid] = s;
    }
}

// ---------------- K2: reduction ----------------
__global__ void k_reduce() {
    __shared__ float red[256];
    int t = threadIdx.x;
    int e = blockIdx.x*64 + (t & 63);
    int q = t >> 6;
    float s = 0.f;
    if (e < 4096) {
#pragma unroll 4
        for (int p = q*64; p < q*64 + 64; p++) s += g_Gpart[p*4096 + e];
    } else {
        int c = e - 4096;
#pragma unroll 4
        for (int p = q*64; p < q*64 + 64; p++) s += g_spart[p*64 + c];
    }
    red[t] = s;
    __syncthreads();
    if (t < 128) red[t] += red[t + 128];
    __syncthreads();
    if (t < 64) {
        float v = red[t] + red[t + 64];
        if (e < 4096) {
            int t16 = e >> 4, k = e & 15;
            int i = ((t16 & 15) << 2) + (k >> 2);
            int j = ((t16 >> 4) << 2) + (k & 3);
            g_G[i*64 + j] = v;
        } else {
            g_s[e - 4096] = v;
        }
    }
}

// ---------------- K3: analytic BN -> folded affine ----------------
__global__ void k_finalize(const float* __restrict__ W1, const float* __restrict__ b1,
                           const float* __restrict__ gamma, const float* __restrict__ beta) {
    __shared__ float Gs[4096], ssh[64], Wc[4][64];
    __shared__ float red1[256], red2[256];
    int tid = threadIdx.x;
    for (int i = tid; i < 4096; i += 256) Gs[i] = g_G[i];
    if (tid < 64) ssh[tid] = g_s[tid];
    {
        int jj = tid >> 6, c = tid & 63;
        Wc[jj][c] = W1[c*HID + blockIdx.x*4 + jj];
    }
    __syncthreads();

    int d = tid & 63, jq = tid >> 6;
    float wdj = Wc[jq][d];
    float qv = 0.f;
#pragma unroll
    for (int c = 0; c < 64; c++) qv += Gs[d*64 + c] * Wc[jq][c];

    red1[tid] = ssh[d]*wdj;
    red2[tid] = qv*wdj;
    __syncthreads();
    for (int off = 32; off > 0; off >>= 1) {
        if (d < off) { red1[tid] += red1[tid+off]; red2[tid] += red2[tid+off]; }
        __syncthreads();
    }
    if (d == 0) {
        int j = blockIdx.x*4 + jq;
        const float invN = 1.f/(float)TOTA;
        float sw = red1[tid], wGw = red2[tid];
        float bj = b1[j];
        float m1 = sw*invN + bj;
        float m2 = (wGw + 2.f*bj*sw)*invN + bj*bj;
        float var = m2 - m1*m1;
        float A = rsqrtf(var + 1e-5f) * gamma[j];
        g_A[j] = A;
        g_B[j] = (bj - m1)*A + beta[j];
    }
}

// ---------------- K4: mma.sync bf16-split GEMM1 + BN + GELU + f32x2 GEMM2 (unchanged) ----------------
#define KA_A    0u
#define KA_B    51200u
#define KA_W2   152576u
#define KA_GA   162816u
#define KA_GB   163840u
#define KA_TOT  164864

__global__ __launch_bounds__(512, 1)
void k_atoms_mma(const float* __restrict__ z, const float* __restrict__ W1,
                 const float* __restrict__ W2, const float* __restrict__ b2,
                 float* __restrict__ out) {
    extern __shared__ char smem[];
    uint32_t sb = smem_u32(smem);
    int tid = threadIdx.x, b = blockIdx.x;
    int lane = tid & 31, w = tid >> 5;

    const float* zp = z + (size_t)b*(128*64);
    for (int it = tid; it < 4096; it += 512) {
        int m = it >> 5, c = (it & 31)*2;
        float2 v = *(const float2*)&zp[m*64 + c];
        __nv_bfloat16 h0 = __float2bfloat16(v.x), h1 = __float2bfloat16(v.y);
        __nv_bfloat16 l0 = __float2bfloat16(v.x - __bfloat162float(h0));
        __nv_bfloat16 l1 = __float2bfloat16(v.y - __bfloat162float(h1));
        __nv_bfloat162 hp(h0, h1), lp(l0, l1);
        uint32_t hh = *reinterpret_cast<uint32_t*>(&hp);
        uint32_t ll = *reinterpret_cast<uint32_t*>(&lp);
        char* base = smem + KA_A + m*400 + c*2;
        *(uint32_t*)(base)       = hh;
        *(uint32_t*)(base + 128) = hh;
        *(uint32_t*)(base + 256) = ll;
    }
    for (int it = tid; it < 8192; it += 512) {
        int j = (it & 127)*2, c = it >> 7;
        float2 wv = *(const float2*)&W1[c*256 + j];
        __nv_bfloat16 h0 = __float2bfloat16(wv.x), h1 = __float2bfloat16(wv.y);
        __nv_bfloat16 l0 = __float2bfloat16(wv.x - __bfloat162float(h0));
        __nv_bfloat16 l1 = __float2bfloat16(wv.y - __bfloat162float(h1));
        __nv_bfloat162 hp(h0, h1), lp(l0, l1);
        uint32_t hh = *reinterpret_cast<uint32_t*>(&hp);
        uint32_t ll = *reinterpret_cast<uint32_t*>(&lp);
        char* base = smem + KA_B + c*528 + j*2;
        *(uint32_t*)(base)           = hh;
        *(uint32_t*)(base + 33792)   = ll;
        *(uint32_t*)(base + 67584)   = hh;
    }
    float* W2sh = (float*)(smem + KA_W2);
    float* gAs  = (float*)(smem + KA_GA);
    float* gBs  = (float*)(smem + KA_GB);
    for (int i = tid; i < 2560; i += 512) W2sh[i] = W2[i];
    if (tid < 256) { gAs[tid] = g_A[tid]; gBs[tid] = g_B[tid]; }
    __syncthreads();

    int mt = w & 7, nh = w >> 3;
    float acc[16][4];
#pragma unroll
    for (int i = 0; i < 16; i++)
#pragma unroll
        for (int x = 0; x < 4; x++) acc[i][x] = 0.f;

    uint32_t aaddr = sb + KA_A + (uint32_t)((mt*16 + (lane & 15))*400 + (lane >> 4)*16);
    uint32_t baddr = sb + KA_B + (uint32_t)((lane & 15)*528 + (nh*128 + (lane >> 4)*8)*2);
#pragma unroll
    for (int s = 0; s < 12; s++) {
        uint32_t ar[4];
        ldmA(ar, aaddr + s*32);
        uint32_t bb = baddr + s*16*528;
#pragma unroll
        for (int i = 0; i < 8; i++) {
            uint32_t br[4];
            ldmBt(br, bb + i*32);
            mma_bf16(acc[2*i],     ar, br[0], br[1]);
            mma_bf16(acc[2*i + 1], ar, br[2], br[3]);
        }
    }
    __syncthreads();

    float* hT = (float*)smem;
    int g = lane >> 2, tig = lane & 3;
    int r1 = mt*16 + g, r2 = r1 + 8;
#pragma unroll
    for (int a = 0; a < 16; a++) {
        int j0 = nh*128 + a*8 + 2*tig;
        float2 A2 = *(float2*)&gAs[j0];
        float2 B2 = *(float2*)&gBs[j0];
        hT[j0*132 + r1]     = gelu_exact(acc[a][0]*A2.x + B2.x);
        hT[(j0+1)*132 + r1] = gelu_exact(acc[a][1]*A2.y + B2.y);
        hT[j0*132 + r2]     = gelu_exact(acc[a][2]*A2.x + B2.x);
        hT[(j0+1)*132 + r2] = gelu_exact(acc[a][3]*A2.y + B2.y);
    }
    __syncthreads();

    for (int it = tid; it < 640; it += 512) {
        int rp = it & 63, k = it >> 6;
        ull a2 = 0ull;
        const float* hp = hT + 2*rp;
        const float* wp = W2sh + k;
#pragma unroll 4
        for (int j = 0; j < 256; j++) {
            ull g2 = *(const ull*)(hp);
            float wv = *wp;
            fma2(a2, g2, pk(wv, wv));
            hp += 132; wp += 10;
        }
        float2 vv = up(a2);
        float bb = b2[k];
        out[((size_t)b*128 + 2*rp)*10 + k]     = vv.x + bb;
        out[((size_t)b*128 + 2*rp + 1)*10 + k] = vv.y + bb;
    }
}

// ---------------- K5: edges via mma.sync — 2 molecules/block ----------------
// smem (bf16 unless noted), stride 72 elems (144 B):
//   WF_HI [320][72] | WF_LO | ZT_HI [64 c][72 a] | ZT_LO | ZA_HI [64 a][72 c] | ZA_LO
//   Y_HI [320 td][72 j] | Y_LO
#define EG_WFH 0u
#define EG_WFL 46080u
#define EG_ZTH 92160u
#define EG_ZTL 101376u
#define EG_ZAH 110592u
#define EG_ZAL 119808u
#define EG_YH  129024u
#define EG_YL  175104u
#define EG_TOT 221184

__global__ __launch_bounds__(512, 1)
void k_edges_mma(float* __restrict__ out) {
    extern __shared__ char smem[];
    uint32_t sb = smem_u32(smem);
    int tid = threadIdx.x, b = blockIdx.x;
    int lane = tid & 31, w = tid >> 5;

    // ---- stage Wf hi/lo ----
    for (int it = tid; it < 10240; it += 512) {
        int td = it >> 5, c2 = (it & 31)*2;
        uint32_t vh = *(const uint32_t*)&g_Wf_hi[td*64 + c2];
        uint32_t vl = *(const uint32_t*)&g_Wf_lo[td*64 + c2];
        *(uint32_t*)(smem + EG_WFH + (td*72 + c2)*2) = vh;
        *(uint32_t*)(smem + EG_WFL + (td*72 + c2)*2) = vl;
    }
    // ---- stage zA (natural) + zT (transposed) ----
    const __nv_bfloat16* zh = g_z_hi + (size_t)b*4096;
    const __nv_bfloat16* zl = g_z_lo + (size_t)b*4096;
    for (int it = tid; it < 2048; it += 512) {
        int a = it >> 5, c2 = (it & 31)*2;
        uint32_t vh = *(const uint32_t*)&zh[a*64 + c2];
        uint32_t vl = *(const uint32_t*)&zl[a*64 + c2];
        *(uint32_t*)(smem + EG_ZAH + (a*72 + c2)*2) = vh;
        *(uint32_t*)(smem + EG_ZAL + (a*72 + c2)*2) = vl;
        __nv_bfloat162 hv = *reinterpret_cast<__nv_bfloat162*>(&vh);
        __nv_bfloat162 lv = *reinterpret_cast<__nv_bfloat162*>(&vl);
        *(__nv_bfloat16*)(smem + EG_ZTH + (c2*72 + a)*2)     = hv.x;
        *(__nv_bfloat16*)(smem + EG_ZTH + ((c2+1)*72 + a)*2) = hv.y;
        *(__nv_bfloat16*)(smem + EG_ZTL + (c2*72 + a)*2)     = lv.x;
        *(__nv_bfloat16*)(smem + EG_ZTL + ((c2+1)*72 + a)*2) = lv.y;
    }
    __syncthreads();

    // ---- Phase 1: Y[320][64] = Wf @ zT ; warp-tile m16 x n64, 3-pass split ----
    for (int mt = w; mt < 20; mt += 16) {
        float acc[8][4];
#pragma unroll
        for (int i = 0; i < 8; i++)
#pragma unroll
            for (int x = 0; x < 4; x++) acc[i][x] = 0.f;

        uint32_t ah[4][4], al[4][4];
        uint32_t abh = sb + EG_WFH + (uint32_t)(((mt*16 + (lane&15))*72 + (lane>>4)*8)*2);
        uint32_t abl = sb + EG_WFL + (uint32_t)(((mt*16 + (lane&15))*72 + (lane>>4)*8)*2);
#pragma unroll
        for (int k = 0; k < 4; k++) {
            ldmA(ah[k], abh + k*32);
            ldmA(al[k], abl + k*32);
        }
#pragma unroll
        for (int k = 0; k < 4; k++) {
            uint32_t bth = sb + EG_ZTH + (uint32_t)(((k*16 + (lane&15))*72 + (lane>>4)*8)*2);
            uint32_t btl = sb + EG_ZTL + (uint32_t)(((k*16 + (lane&15))*72 + (lane>>4)*8)*2);
#pragma unroll
            for (int n = 0; n < 4; n++) {      // n16 groups
                uint32_t bh[4], bl[4];
                ldmBt(bh, bth + n*32);
                ldmBt(bl, btl + n*32);
                mma_bf16(acc[2*n],   ah[k], bh[0], bh[1]);
                mma_bf16(acc[2*n+1], ah[k], bh[2], bh[3]);
                mma_bf16(acc[2*n],   al[k], bh[0], bh[1]);
                mma_bf16(acc[2*n+1], al[k], bh[2], bh[3]);
                mma_bf16(acc[2*n],   ah[k], bl[0], bl[1]);
                mma_bf16(acc[2*n+1], ah[k], bl[2], bl[3]);
            }
        }
        // epilogue: split Y -> bf16 hi/lo, natural [td][j] store
        int g = lane >> 2, tig = lane & 3;
        int r1 = mt*16 + g;
#pragma unroll
        for (int n8 = 0; n8 < 8; n8++) {
            int col = n8*8 + 2*tig;
#pragma unroll
            for (int half = 0; half < 2; half++) {
                int row = r1 + half*8;
                float v0 = acc[n8][2*half], v1 = acc[n8][2*half + 1];
                __nv_bfloat16 h0 = __float2bfloat16(v0), h1 = __float2bfloat16(v1);
                __nv_bfloat16 l0 = __float2bfloat16(v0 - __bfloat162float(h0));
                __nv_bfloat16 l1 = __float2bfloat16(v1 - __bfloat162float(h1));
                __nv_bfloat162 hp(h0, h1), lp(l0, l1);
                *(uint32_t*)(smem + EG_YH + (row*72 + col)*2) = *(uint32_t*)&hp;
                *(uint32_t*)(smem + EG_YL + (row*72 + col)*2) = *(uint32_t*)&lp;
            }
        }
    }
    __syncthreads();

    // ---- Phase 2: warp = (molh, i-16-tile, j-8-tile); all 5 t in-warp ----
    {
        int molh = w >> 3, mt2 = (w >> 2) & 1, jn = w & 3;
        uint32_t ah[4][4], al[4][4];
        uint32_t off = (uint32_t)(((molh*32 + mt2*16 + (lane&15))*72 + (lane>>4)*8)*2);
#pragma unroll
        for (int k = 0; k < 4; k++) {
            ldmA(ah[k], sb + EG_ZAH + off + k*32);
            ldmA(al[k], sb + EG_ZAL + off + k*32);
        }
        float acc[5][4];
#pragma unroll
        for (int t = 0; t < 5; t++)
#pragma unroll
            for (int x = 0; x < 4; x++) acc[t][x] = 0.f;

        int jcol = molh*32 + jn*8;
#pragma unroll
        for (int t = 0; t < 5; t++) {
#pragma unroll
            for (int k = 0; k < 4; k++) {
                uint32_t row = (uint32_t)(t*64 + k*16 + (lane & 15));
                uint32_t bh[2], bl[2];
                ldmBt2(bh, sb + EG_YH + (row*72 + jcol)*2);
                ldmBt2(bl, sb + EG_YL + (row*72 + jcol)*2);
                mma_bf16(acc[t], ah[k], bh[0], bh[1]);
                mma_bf16(acc[t], al[k], bh[0], bh[1]);
                mma_bf16(acc[t], ah[k], bl[0], bl[1]);
            }
        }

        // softmax epilogue (all in registers)
        int g = lane >> 2, tig = lane & 3;
        int mol = b*2 + molh;
        float* eout = out + ATOM_OUT + mol*(NEDGE*5);
#pragma unroll
        for (int pos = 0; pos < 4; pos++) {
            int i = mt2*16 + g + (pos >> 1)*8;
            int j = jn*8 + 2*tig + (pos & 1);
            if (i < j) {
                float v0 = acc[0][pos], v1 = acc[1][pos], v2 = acc[2][pos],
                      v3 = acc[3][pos], v4 = acc[4][pos];
                float m = fmaxf(fmaxf(fmaxf(v0, v1), fmaxf(v2, v3)), v4);
                float e0 = __expf(v0-m), e1 = __expf(v1-m), e2 = __expf(v2-m),
                      e3 = __expf(v3-m), e4 = __expf(v4-m);
                float inv = 1.f/(e0+e1+e2+e3+e4);
                int e = 31*i - (i*(i-1))/2 + (j - i - 1);
                float* dst = eout + e*5;
                dst[0] = e0*inv; dst[1] = e1*inv; dst[2] = e2*inv;
                dst[3] = e3*inv; dst[4] = e4*inv;
            }
        }
    }
}

// ---------------- launch ----------------
extern "C" void kernel_launch(void* const* d_in, const int* in_sizes, int n_in,
                              void* d_out, int out_size) {
    const float* z  = (const float*)d_in[0];
    const float* W1 = (const float*)d_in[1];
    const float* b1 = (const float*)d_in[2];
    const float* gm = (const float*)d_in[3];
    const float* bt = (const float*)d_in[4];
    const float* W2 = (const float*)d_in[5];
    const float* b2 = (const float*)d_in[6];
    const float* bm = (const float*)d_in[7];
    float* out = (float*)d_out;
    (void)in_sizes; (void)n_in; (void)out_size;

    cudaFuncSetAttribute(k_atoms_mma, cudaFuncAttributeMaxDynamicSharedMemorySize, KA_TOT);
    cudaFuncSetAttribute(k_edges_mma, cudaFuncAttributeMaxDynamicSharedMemorySize, EG_TOT);

    k_prep_stats<<<848, 256>>>(z, bm);
    k_reduce    <<<65,  256>>>();
    k_finalize  <<<64,  256>>>(W1, b1, gm, bt);
    k_atoms_mma <<<256, 512, KA_TOT>>>(z, W1, W2, b2, out);
    k_edges_mma <<<512, 512, EG_TOT>>>(out);
}